// round 4
// baseline (speedup 1.0000x reference)
#include <cuda_runtime.h>
#include <cstdint>
#include <cstddef>

// Problem constants (fixed by the dataset)
#define K_   512      // num_embeddings
#define D_   64       // embedding_dim
#define N_   262144   // H*W = 512*512
#define BM   128      // points per block
#define KC   128      // codes per chunk
#define NCH  (K_ / KC)
#define THREADS 256
#define ZST  132      // szT row stride in floats (16B aligned, de-conflicts column reads)

// ---- device scratch (no allocations allowed) ----
__device__ float g_bcs[K_];                       // batch cluster size accumulator
__device__ float g_bes[K_ * D_];                  // batch embedding sum accumulator
__device__ unsigned long long g_scd[D_ * K_];     // codebook, transposed + duplicated (c,c) pairs
__device__ float g_bsq[K_];                       // ||c_k||^2
__device__ int   g_idx[N_];                       // winning index per point

// ---------------- packed f32x2 helpers ----------------
__device__ __forceinline__ unsigned long long pack2(float lo, float hi) {
    unsigned long long r;
    asm("mov.b64 %0, {%1, %2};" : "=l"(r) : "f"(lo), "f"(hi));
    return r;
}
__device__ __forceinline__ void unpack2(unsigned long long v, float& lo, float& hi) {
    asm("mov.b64 {%0, %1}, %2;" : "=f"(lo), "=f"(hi) : "l"(v));
}
__device__ __forceinline__ void fma2(unsigned long long& acc, unsigned long long a,
                                     unsigned long long b) {
    asm("fma.rn.f32x2 %0, %1, %2, %0;" : "+l"(acc) : "l"(a), "l"(b));
}

// ---------------- prep: zero accumulators, build dup-transposed codebook, b_sq ----------------
__global__ void vq_prep(const float* __restrict__ cb) {
    int i = blockIdx.x * blockDim.x + threadIdx.x;
    if (i < K_ * D_) {
        int k = i / D_, d = i % D_;
        float v = cb[i];                       // coalesced read
        g_scd[d * K_ + k] = pack2(v, v);       // scattered 8B write (once, cheap)
        g_bes[i] = 0.0f;
    }
    if (i < K_) {
        g_bcs[i] = 0.0f;
        const float* row = cb + i * D_;
        // reference: jnp.sum(c*c, axis=1) -> mul then add, ascending, NO fma
        float s = 0.0f;
#pragma unroll
        for (int d = 0; d < D_; ++d) s = __fadd_rn(s, __fmul_rn(row[d], row[d]));
        g_bsq[i] = s;
    }
}

// ---------------- main: distances + argmin + z_q_st ----------------
extern __shared__ float smem[];

__global__ void __launch_bounds__(THREADS, 2) vq_main(
    const float* __restrict__ z, const float* __restrict__ cb,
    float* __restrict__ o_zq, float* __restrict__ o_idx, float* __restrict__ o_mind)
{
    float* szT = smem;                                  // [D_][ZST]  z tile, d-major
    unsigned long long* scd = (unsigned long long*)(smem + D_ * ZST);  // [D_][KC] dup pairs
    float* sbs  = (float*)(scd + D_ * KC);              // [KC] b_sq chunk
    float* sasq = sbs + KC;                             // [BM] a_sq per point
    int*   sidx = (int*)(sasq + BM);                    // [BM] winning index
    // reduction arrays alias scd after the last chunk is consumed
    float* redv = (float*)scd;                          // [16][BM]
    int*   redi = (int*)((float*)scd + 16 * BM);        // [16][BM]

    const int tid = threadIdx.x;
    const int tx = tid & 15;           // code group: codes tx*8..tx*8+7
    const int ty = tid >> 4;           // point group: points ty*8..ty*8+7 (4 packed pairs)
    const int p0 = blockIdx.x * BM;

    // load z tile transposed: szT[d][p] = z[p][d]
    const float4* zg4 = (const float4*)(z + (size_t)p0 * D_);
    for (int i = tid; i < BM * D_ / 4; i += THREADS) {
        int p = i >> 4, q = i & 15;
        float4 v = zg4[p * 16 + q];
        int d = q * 4;
        szT[(d + 0) * ZST + p] = v.x;
        szT[(d + 1) * ZST + p] = v.y;
        szT[(d + 2) * ZST + p] = v.z;
        szT[(d + 3) * ZST + p] = v.w;
    }
    __syncthreads();

    // a_sq per point: sequential ascending, mul+add (NO fma) — replicates XLA reduction.
    // Column read szT[d][p]: 32 consecutive p -> distinct banks (ZST%32==4 pattern ok).
    if (tid < BM) {
        float a = 0.0f;
#pragma unroll
        for (int d = 0; d < D_; ++d) {
            float v = szT[d * ZST + tid];
            a = __fadd_rn(a, __fmul_rn(v, v));
        }
        sasq[tid] = a;
    }

    float bestv[8];
    int   besti[8];
#pragma unroll
    for (int p = 0; p < 8; ++p) { bestv[p] = 3.4e38f; besti[p] = 0x7fffffff; }

    for (int ch = 0; ch < NCH; ++ch) {
        if (ch) __syncthreads();  // previous chunk fully consumed
        // copy codebook chunk (already duplicated) from global: pure float4 copy
        {
            const float4* gs = (const float4*)g_scd;   // row d = 256 float4
            for (int i = tid; i < D_ * KC / 2; i += THREADS) {  // KC u64 = KC/2 float4 per row
                int d = i >> 6, j = i & 63;
                float4 v = gs[d * (K_ / 2) + ch * (KC / 2) + j];
                *((float4*)(scd + d * KC) + j) = v;
            }
            if (tid < KC) sbs[tid] = g_bsq[ch * KC + tid];
        }
        __syncthreads();  // chunk (and on ch==0: sasq) visible

        // dot = sequential ascending-d fma chain; lanes = two adjacent points
        unsigned long long acc[8][4];
#pragma unroll
        for (int c = 0; c < 8; ++c)
#pragma unroll
            for (int pp = 0; pp < 4; ++pp) acc[c][pp] = 0ull;

#pragma unroll 4
        for (int d = 0; d < D_; ++d) {
            // 4 point-pairs: 2x LDS.128, pairs come out pre-packed
            const ulonglong2* zp2 = (const ulonglong2*)(szT + d * ZST + ty * 8);
            ulonglong2 za = zp2[0], zb = zp2[1];
            unsigned long long zp[4] = { za.x, za.y, zb.x, zb.y };
            // 8 duplicated codes: 4x LDS.128
            const ulonglong2* cp2 = (const ulonglong2*)(scd + d * KC + tx * 8);
            ulonglong2 c0 = cp2[0], c1 = cp2[1], c2 = cp2[2], c3 = cp2[3];
            unsigned long long cd[8] = { c0.x, c0.y, c1.x, c1.y, c2.x, c2.y, c3.x, c3.y };
#pragma unroll
            for (int c = 0; c < 8; ++c)
#pragma unroll
                for (int pp = 0; pp < 4; ++pp) fma2(acc[c][pp], zp[pp], cd[c]);
        }

        // epilogue: dist = fl(fl(asq - 2*dot) + bsq); ascending c => strict < keeps first idx
#pragma unroll
        for (int c = 0; c < 8; ++c) {
            float bs = sbs[tx * 8 + c];
            int cidx = ch * KC + tx * 8 + c;
#pragma unroll
            for (int pp = 0; pp < 4; ++pp) {
                float lo, hi;
                unpack2(acc[c][pp], lo, hi);
                float a0 = sasq[ty * 8 + 2 * pp];
                float a1 = sasq[ty * 8 + 2 * pp + 1];
                // fmaf(-2,dot,asq) == fsub(asq, 2*dot) bitwise (2*dot exact)
                float d0 = __fadd_rn(__fmaf_rn(-2.0f, lo, a0), bs);
                float d1 = __fadd_rn(__fmaf_rn(-2.0f, hi, a1), bs);
                if (d0 < bestv[2 * pp])     { bestv[2 * pp] = d0;     besti[2 * pp] = cidx; }
                if (d1 < bestv[2 * pp + 1]) { bestv[2 * pp + 1] = d1; besti[2 * pp + 1] = cidx; }
            }
        }
    }

    __syncthreads();  // all reads of scd done -> reuse as reduction space
#pragma unroll
    for (int p = 0; p < 8; ++p) {
        redv[tx * BM + ty * 8 + p] = bestv[p];
        redi[tx * BM + ty * 8 + p] = besti[p];
    }
    __syncthreads();

    if (tid < BM) {
        int p = tid;
        float bv = redv[p];
        int bi = redi[p];
#pragma unroll
        for (int t = 1; t < 16; ++t) {
            float v = redv[t * BM + p];
            int ii = redi[t * BM + p];
            if (v < bv || (v == bv && ii < bi)) { bv = v; bi = ii; }
        }
        o_idx[p0 + p]  = (float)bi;
        o_mind[p0 + p] = bv;
        sidx[p] = bi;
        g_idx[p0 + p] = bi;
    }
    __syncthreads();

    // z_q_st = z_e + (z_q - z_e), non-fused, mirroring the reference
    for (int i = tid; i < BM * D_; i += THREADS) {
        int p = i >> 6, d = i & 63;
        int bi = sidx[p];
        float ze = szT[d * ZST + p];
        float zq = cb[bi * D_ + d];
        o_zq[(size_t)(p0 + p) * D_ + d] = __fadd_rn(ze, __fsub_rn(zq, ze));
    }
}

// ---------------- stats: smem-aggregated scatter-add, one wave ----------------
#define STATS_BLOCKS 148
extern __shared__ float smem_s[];

__global__ void __launch_bounds__(256, 1) vq_stats(const float* __restrict__ z)
{
    float* sacc = smem_s;            // [K_][D_] = 32768 floats
    float* scnt = sacc + K_ * D_;    // [K_]

    const int tid = threadIdx.x;
    for (int i = tid; i < K_ * D_; i += 256) sacc[i] = 0.0f;
    for (int i = tid; i < K_; i += 256) scnt[i] = 0.0f;
    __syncthreads();

    const int per = (N_ + gridDim.x - 1) / gridDim.x;
    const int pstart = blockIdx.x * per;
    const int pend = min(pstart + per, N_);
    const int w = tid >> 5, lane = tid & 31;

    for (int p = pstart + w; p < pend; p += 8) {
        int bi = g_idx[p];
        float v0 = z[(size_t)p * D_ + lane];
        float v1 = z[(size_t)p * D_ + 32 + lane];
        atomicAdd(&sacc[bi * D_ + lane], v0);
        atomicAdd(&sacc[bi * D_ + 32 + lane], v1);
        if (lane == 0) atomicAdd(&scnt[bi], 1.0f);
    }
    __syncthreads();

    // flush non-zero entries to global (skips ~75% of rows untouched by this block)
    for (int i = tid; i < K_ * D_; i += 256) {
        float v = sacc[i];
        if (v != 0.0f) atomicAdd(&g_bes[i], v);
    }
    for (int i = tid; i < K_; i += 256) {
        float v = scnt[i];
        if (v != 0.0f) atomicAdd(&g_bcs[i], v);
    }
}

// ---------------- finalize: EMA update + new codebook ----------------
__global__ void vq_final(const float* __restrict__ ema_cs, const float* __restrict__ ema_es,
                         float* __restrict__ o_cb, float* __restrict__ o_cs,
                         float* __restrict__ o_es)
{
    int i = blockIdx.x * blockDim.x + threadIdx.x;
    if (i < K_) {
        o_cs[i] = __fadd_rn(__fmul_rn(0.99f, ema_cs[i]), __fmul_rn(0.01f, g_bcs[i]));
    }
    if (i < K_ * D_) {
        int k = i / D_;
        float ncs = __fadd_rn(__fmul_rn(0.99f, ema_cs[k]), __fmul_rn(0.01f, g_bcs[k]));
        float nes = __fadd_rn(__fmul_rn(0.99f, ema_es[i]), __fmul_rn(0.01f, g_bes[i]));
        o_es[i] = nes;
        o_cb[i] = __fdiv_rn(nes, __fadd_rn(ncs, 1e-5f));
    }
}

// ---------------- launcher ----------------
extern "C" void kernel_launch(void* const* d_in, const int* in_sizes, int n_in,
                              void* d_out, int out_size)
{
    const float* z      = (const float*)d_in[0];  // [512,512,64]
    const float* cb     = (const float*)d_in[1];  // [512,64]
    const float* ema_cs = (const float*)d_in[2];  // [512]
    const float* ema_es = (const float*)d_in[3];  // [512,64]

    float* out    = (float*)d_out;
    float* o_zq   = out;                              // N*D
    float* o_idx  = o_zq + (size_t)N_ * D_;           // N
    float* o_mind = o_idx + N_;                       // N
    float* o_cb   = o_mind + N_;                      // K*D
    float* o_cs   = o_cb + (size_t)K_ * D_;           // K
    float* o_es   = o_cs + K_;                        // K*D

    (void)in_sizes; (void)n_in; (void)out_size;

    vq_prep<<<(K_ * D_ + 255) / 256, 256>>>(cb);

    // vq_main smem: szT + scd + sbs + sasq + sidx
    const size_t smem_main = (size_t)(D_ * ZST) * 4 + (size_t)(D_ * KC) * 8
                           + (size_t)(KC + BM) * 4 + (size_t)BM * 4;  // 100,864 B
    cudaFuncSetAttribute(vq_main, cudaFuncAttributeMaxDynamicSharedMemorySize,
                         (int)smem_main);
    vq_main<<<N_ / BM, THREADS, smem_main>>>(z, cb, o_zq, o_idx, o_mind);

    const size_t smem_stats = (size_t)(K_ * D_ + K_) * 4;  // 133,120 B
    cudaFuncSetAttribute(vq_stats, cudaFuncAttributeMaxDynamicSharedMemorySize,
                         (int)smem_stats);
    vq_stats<<<STATS_BLOCKS, 256, smem_stats>>>(z);

    vq_final<<<(K_ * D_ + 255) / 256, 256>>>(ema_cs, ema_es, o_cb, o_cs, o_es);
}

// round 7
// speedup vs baseline: 2.5591x; 2.5591x over previous
#include <cuda_runtime.h>
#include <cstdint>
#include <cstddef>

// Problem constants (fixed by the dataset)
#define K_   512      // num_embeddings
#define D_   64       // embedding_dim
#define N_   262144   // H*W = 512*512
#define BM   128      // points per block
#define KC   128      // codes per chunk
#define NCH  (K_ / KC)
#define THREADS 256
#define ZST  132      // szT row stride in floats (16B aligned)

// ---- device scratch (no allocations allowed) ----
__device__ float g_bcs[K_];                       // batch cluster size accumulator
__device__ float g_bes[K_ * D_];                  // batch embedding sum accumulator
__device__ unsigned long long g_scd[D_ * K_];     // dup (c,c) codes, granule-interleaved per chunk
__device__ float g_bsq[K_];                       // ||c_k||^2

// ---------------- packed f32x2 helpers ----------------
__device__ __forceinline__ unsigned long long pack2(float lo, float hi) {
    unsigned long long r;
    asm("mov.b64 %0, {%1, %2};" : "=l"(r) : "f"(lo), "f"(hi));
    return r;
}
__device__ __forceinline__ void unpack2(unsigned long long v, float& lo, float& hi) {
    asm("mov.b64 {%0, %1}, %2;" : "=f"(lo), "=f"(hi) : "l"(v));
}
__device__ __forceinline__ void fma2(unsigned long long& acc, unsigned long long a,
                                     unsigned long long b) {
    asm("fma.rn.f32x2 %0, %1, %2, %0;" : "+l"(acc) : "l"(a), "l"(b));
}

// ---------------- prep ----------------
// Layout of g_scd row d, chunk ch (128 consecutive u64):
//   granule g = j*16 + tx  (16B = 2 u64) holds codes {ch*128 + 32j + 2tx, +1}
//   so u64 position = d*K_ + ch*128 + (j*16 + tx)*2 + (k&1)
__global__ void vq_prep(const float* __restrict__ cb) {
    int i = blockIdx.x * blockDim.x + threadIdx.x;
    if (i < K_ * D_) {
        int k = i / D_, d = i % D_;
        float v = cb[i];                       // coalesced read
        int ch = k >> 7;
        int lp = (k & 127) >> 1;               // local pair 0..63
        int tx = lp & 15, j = lp >> 4;
        int pos = d * K_ + ch * 128 + (j * 16 + tx) * 2 + (k & 1);
        g_scd[pos] = pack2(v, v);
        g_bes[i] = 0.0f;
    }
    if (i < K_) {
        g_bcs[i] = 0.0f;
        const float* row = cb + i * D_;
        // reference: jnp.sum(c*c, axis=1) -> mul then add, ascending, NO fma
        float s = 0.0f;
#pragma unroll
        for (int d = 0; d < D_; ++d) s = __fadd_rn(s, __fmul_rn(row[d], row[d]));
        g_bsq[i] = s;
    }
}

// ---------------- main: distances + argmin + z_q_st + inline stats ----------------
extern __shared__ float smem[];

__global__ void __launch_bounds__(THREADS, 2) vq_main(
    const float* __restrict__ z, const float* __restrict__ cb,
    float* __restrict__ o_zq, float* __restrict__ o_idx, float* __restrict__ o_mind)
{
    float* szT = smem;                                  // [D_][ZST]  z tile, d-major
    unsigned long long* scd = (unsigned long long*)(smem + D_ * ZST);  // [D_][KC] interleaved
    float* sbs  = (float*)(scd + D_ * KC);              // [KC] b_sq chunk (chunk-local index)
    float* sasq = sbs + KC;                             // [BM] a_sq per point
    int*   sidx = (int*)(sasq + BM);                    // [BM] winning index
    // reduction arrays alias scd after the last chunk is consumed
    float* redv = (float*)scd;                          // [16][BM]
    int*   redi = (int*)((float*)scd + 16 * BM);        // [16][BM]

    const int tid = threadIdx.x;
    const int tx = tid & 15;           // code lane
    const int ty = tid >> 4;           // point group: points ty*8..ty*8+7 (4 packed pairs)
    const int p0 = blockIdx.x * BM;

    // load z tile transposed: szT[d][p] = z[p][d]
    const float4* zg4 = (const float4*)(z + (size_t)p0 * D_);
    for (int i = tid; i < BM * D_ / 4; i += THREADS) {
        int p = i >> 4, q = i & 15;
        float4 v = zg4[p * 16 + q];
        int d = q * 4;
        szT[(d + 0) * ZST + p] = v.x;
        szT[(d + 1) * ZST + p] = v.y;
        szT[(d + 2) * ZST + p] = v.z;
        szT[(d + 3) * ZST + p] = v.w;
    }
    __syncthreads();

    // a_sq per point: sequential ascending, mul+add (NO fma) — replicates XLA reduction.
    if (tid < BM) {
        float a = 0.0f;
#pragma unroll
        for (int d = 0; d < D_; ++d) {
            float v = szT[d * ZST + tid];
            a = __fadd_rn(a, __fmul_rn(v, v));
        }
        sasq[tid] = a;
    }

    float bestv[8];
    int   besti[8];
#pragma unroll
    for (int p = 0; p < 8; ++p) { bestv[p] = 3.4e38f; besti[p] = 0x7fffffff; }

    for (int ch = 0; ch < NCH; ++ch) {
        if (ch) __syncthreads();  // previous chunk fully consumed
        // copy codebook chunk (dup + interleaved) from global: pure float4 copy
        {
            const float4* gs = (const float4*)g_scd;   // row d = K_/2 float4
            for (int i = tid; i < D_ * KC / 2; i += THREADS) {
                int d = i >> 6, j = i & 63;
                float4 v = gs[d * (K_ / 2) + ch * (KC / 2) + j];
                *((float4*)(scd + d * KC) + j) = v;
            }
            if (tid < KC) sbs[tid] = g_bsq[ch * KC + tid];
        }
        __syncthreads();  // chunk (and on ch==0: sasq) visible

        // dot = sequential ascending-d fma chain; f32x2 lanes = two adjacent points
        unsigned long long acc[8][4];
#pragma unroll
        for (int c = 0; c < 8; ++c)
#pragma unroll
            for (int pp = 0; pp < 4; ++pp) acc[c][pp] = 0ull;

#pragma unroll 4
        for (int d = 0; d < D_; ++d) {
            // 4 point-pairs: 2x LDS.128 (broadcast within warp)
            const ulonglong2* zp2 = (const ulonglong2*)(szT + d * ZST + ty * 8);
            ulonglong2 za = zp2[0], zb = zp2[1];
            unsigned long long zp[4] = { za.x, za.y, zb.x, zb.y };
            // 8 codes as 4 granules at 16B lane stride (conflict-free):
            // granule j at u64 offset d*KC + (j*16 + tx)*2
            const ulonglong2* cg = (const ulonglong2*)(scd + d * KC);
            ulonglong2 c0 = cg[0 * 16 + tx];
            ulonglong2 c1 = cg[1 * 16 + tx];
            ulonglong2 c2 = cg[2 * 16 + tx];
            ulonglong2 c3 = cg[3 * 16 + tx];
            unsigned long long cd[8] = { c0.x, c0.y, c1.x, c1.y,
                                         c2.x, c2.y, c3.x, c3.y };
#pragma unroll
            for (int c = 0; c < 8; ++c)
#pragma unroll
                for (int pp = 0; pp < 4; ++pp) fma2(acc[c][pp], zp[pp], cd[c]);
        }

        // epilogue: dist = fl(fl(asq - 2*dot) + bsq)
        // thread's code (j, e): cidx = ch*128 + 32j + 2tx + e
#pragma unroll
        for (int c = 0; c < 8; ++c) {           // c = j*2 + e
            int j = c >> 1, e = c & 1;
            int lk = 32 * j + 2 * tx + e;       // chunk-local code index
            float bs = sbs[lk];
            int cidx = ch * KC + lk;
#pragma unroll
            for (int pp = 0; pp < 4; ++pp) {
                float lo, hi;
                unpack2(acc[c][pp], lo, hi);
                float a0 = sasq[ty * 8 + 2 * pp];
                float a1 = sasq[ty * 8 + 2 * pp + 1];
                float d0 = __fadd_rn(__fmaf_rn(-2.0f, lo, a0), bs);
                float d1 = __fadd_rn(__fmaf_rn(-2.0f, hi, a1), bs);
                if (d0 < bestv[2 * pp])     { bestv[2 * pp] = d0;     besti[2 * pp] = cidx; }
                if (d1 < bestv[2 * pp + 1]) { bestv[2 * pp + 1] = d1; besti[2 * pp + 1] = cidx; }
            }
        }
    }

    __syncthreads();  // all reads of scd done -> reuse as reduction space
#pragma unroll
    for (int p = 0; p < 8; ++p) {
        redv[tx * BM + ty * 8 + p] = bestv[p];
        redi[tx * BM + ty * 8 + p] = besti[p];
    }
    __syncthreads();

    if (tid < BM) {
        int p = tid;
        float bv = redv[p];
        int bi = redi[p];
#pragma unroll
        for (int t = 1; t < 16; ++t) {
            float v = redv[t * BM + p];
            int ii = redi[t * BM + p];
            if (v < bv || (v == bv && ii < bi)) { bv = v; bi = ii; }
        }
        o_idx[p0 + p]  = (float)bi;
        o_mind[p0 + p] = bv;
        sidx[p] = bi;
        atomicAdd(&g_bcs[bi], 1.0f);
    }
    __syncthreads();

    // z_q_st = z_e + (z_q - z_e), non-fused, mirroring the reference; EMA scatter inline
    for (int i = tid; i < BM * D_; i += THREADS) {
        int p = i >> 6, d = i & 63;
        int bi = sidx[p];
        float ze = szT[d * ZST + p];
        float zq = cb[bi * D_ + d];
        o_zq[(size_t)(p0 + p) * D_ + d] = __fadd_rn(ze, __fsub_rn(zq, ze));
        atomicAdd(&g_bes[bi * D_ + d], ze);
    }
}

// ---------------- finalize: EMA update + new codebook ----------------
__global__ void vq_final(const float* __restrict__ ema_cs, const float* __restrict__ ema_es,
                         float* __restrict__ o_cb, float* __restrict__ o_cs,
                         float* __restrict__ o_es)
{
    int i = blockIdx.x * blockDim.x + threadIdx.x;
    if (i < K_) {
        o_cs[i] = __fadd_rn(__fmul_rn(0.99f, ema_cs[i]), __fmul_rn(0.01f, g_bcs[i]));
    }
    if (i < K_ * D_) {
        int k = i / D_;
        float ncs = __fadd_rn(__fmul_rn(0.99f, ema_cs[k]), __fmul_rn(0.01f, g_bcs[k]));
        float nes = __fadd_rn(__fmul_rn(0.99f, ema_es[i]), __fmul_rn(0.01f, g_bes[i]));
        o_es[i] = nes;
        o_cb[i] = __fdiv_rn(nes, __fadd_rn(ncs, 1e-5f));
    }
}

// ---------------- launcher ----------------
extern "C" void kernel_launch(void* const* d_in, const int* in_sizes, int n_in,
                              void* d_out, int out_size)
{
    const float* z      = (const float*)d_in[0];  // [512,512,64]
    const float* cb     = (const float*)d_in[1];  // [512,64]
    const float* ema_cs = (const float*)d_in[2];  // [512]
    const float* ema_es = (const float*)d_in[3];  // [512,64]

    float* out    = (float*)d_out;
    float* o_zq   = out;                              // N*D
    float* o_idx  = o_zq + (size_t)N_ * D_;           // N
    float* o_mind = o_idx + N_;                       // N
    float* o_cb   = o_mind + N_;                      // K*D
    float* o_cs   = o_cb + (size_t)K_ * D_;           // K
    float* o_es   = o_cs + K_;                        // K*D

    (void)in_sizes; (void)n_in; (void)out_size;

    vq_prep<<<(K_ * D_ + 255) / 256, 256>>>(cb);

    // vq_main smem: szT + scd + sbs + sasq + sidx = 100,864 B
    const size_t smem_main = (size_t)(D_ * ZST) * 4 + (size_t)(D_ * KC) * 8
                           + (size_t)(KC + BM) * 4 + (size_t)BM * 4;
    cudaFuncSetAttribute(vq_main, cudaFuncAttributeMaxDynamicSharedMemorySize,
                         (int)smem_main);
    vq_main<<<N_ / BM, THREADS, smem_main>>>(z, cb, o_zq, o_idx, o_mind);

    vq_final<<<(K_ * D_ + 255) / 256, 256>>>(ema_cs, ema_es, o_cb, o_cs, o_es);
}